// round 13
// baseline (speedup 1.0000x reference)
#include <cuda_runtime.h>
#include <math.h>
#include <stdint.h>

// ---------------- problem constants ----------------
#define BBATCH 4
#define TT     24
#define NST    128
#define FINF   64
#define CC     256
#define LL     3
#define KK     3
#define GHH    2
#define NHH    4
#define EE     1024
#define NG     (BBATCH*TT)        // 96
#define NNODE  (NG*NST)           // 12288
#define MAXE   64
#define ECAP   24

// inverse/forward 64-tile permutation (involution): swap 3-bit fields
#define PERM64(p) ((((p) & 7) << 3) | ((p) >> 3))

// ---------------- static scratch ----------------
__device__ int d_csr_ptr[NST+1];
__device__ int d_csr_eid[EE];

#define OFF_H    ((size_t)0)
#define OFF_H2   (OFF_H    + (size_t)NNODE*CC)
#define OFF_SKIP (OFF_H2   + (size_t)NNODE*CC)
#define OFF_Y    (OFF_SKIP + (size_t)NNODE*CC)
#define OFF_XLR  (OFF_Y    + (size_t)NNODE*CC)
#define OFF_QKV  (OFF_XLR  + (size_t)NNODE*1024)
#define OFF_AO   (OFF_QKV  + (size_t)NNODE*768)
#define OFF_HREF (OFF_AO   + (size_t)NNODE*CC)
#define OFF_BQKV (OFF_HREF + (size_t)NNODE*CC)
#define OFF_BES  (OFF_BQKV + (size_t)768)
#define TOTF     (OFF_BES  + (size_t)512)
__device__ float d_buf[TOTF];

// all weights tf32-rounded float, tile-permuted layout
#define WF_WT   ((size_t)0)                        // 3*768*256 conv (transposed)
#define WF_WLR  (WF_WT   + (size_t)LL*KK*CC*CC)    // 3*256*1024
#define WF_QKV  (WF_WLR  + (size_t)LL*CC*1024)     // 256*768
#define WF_ES   (WF_QKV  + (size_t)CC*768)         // 64*512 packed enc|skip
#define WF_WO   (WF_ES   + (size_t)FINF*512)       // 256*256
#define WF_GATE (WF_WO   + (size_t)CC*CC)
#define TOTWF   (WF_GATE + (size_t)CC*CC)
__device__ float d_wbuf1[TOTWF];

// ---------------- helpers ----------------
__device__ __forceinline__ float tf32r(float x) {
    uint32_t u;
    asm("cvt.rna.tf32.f32 %0, %1;" : "=r"(u) : "f"(x));
    return __uint_as_float(u);
}
#define U32F(f) __float_as_uint(f)

__device__ __forceinline__ void mma8(float4& d, const uint32_t a[4],
                                     uint32_t b0, uint32_t b1) {
    asm volatile(
        "mma.sync.aligned.m16n8k8.row.col.f32.tf32.tf32.f32 "
        "{%0,%1,%2,%3},{%4,%5,%6,%7},{%8,%9},{%0,%1,%2,%3};"
        : "+f"(d.x), "+f"(d.y), "+f"(d.z), "+f"(d.w)
        : "r"(a[0]), "r"(a[1]), "r"(a[2]), "r"(a[3]), "r"(b0), "r"(b1));
}

// one ldmatrix.x4 loads the full m16k8 tf32 A fragment (4x 8x4-f32 tiles)
__device__ __forceinline__ void ldmA(uint32_t a[4], uint32_t addr) {
    asm volatile("ldmatrix.sync.aligned.m8n8.x4.shared.b16 {%0,%1,%2,%3}, [%4];"
                 : "=r"(a[0]), "=r"(a[1]), "=r"(a[2]), "=r"(a[3]) : "r"(addr));
}

__device__ __forceinline__ void cpa16(uint32_t dst, const void* src) {
    asm volatile("cp.async.ca.shared.global [%0], [%1], 16;" :: "r"(dst), "l"(src));
}
__device__ __forceinline__ void cpa16z(uint32_t dst, const void* src, int sz) {
    asm volatile("cp.async.ca.shared.global [%0], [%1], 16, %2;"
                 :: "r"(dst), "l"(src), "r"(sz));
}
#define CPA_COMMIT() asm volatile("cp.async.commit_group;" ::: "memory")
#define CPA_WAIT(n)  asm volatile("cp.async.wait_group %0;" :: "n"(n) : "memory")

// ---------------- deterministic CSR of base graph ----------------
__global__ void build_csr_kernel(const int* __restrict__ edge) {
    const int* dst = edge + EE;
    int n = threadIdx.x;
    __shared__ int counts[NST];
    int cnt = 0;
    for (int e = 0; e < EE; e++) if (dst[e] == n) cnt++;
    counts[n] = cnt;
    __syncthreads();
    if (n == 0) {
        int s = 0;
        for (int i = 0; i < NST; i++) { d_csr_ptr[i] = s; s += counts[i]; }
        d_csr_ptr[NST] = s;
    }
    __syncthreads();
    int p = d_csr_ptr[n];
    for (int e = 0; e < EE; e++) if (dst[e] == n) d_csr_eid[p++] = e;  // stable
}

// ---------------- tf32 GEMM: BM=128 BN=64 BK=16, ldmatrix-A + permuted-B -----
// kt loop unrolled by 2: compile-time stage, hoisted addressing.
// ACVT : 1 = RNA-round A fragments (conv spine), 0 = raw fp32 bits
// EPI: 0 = +bias, 3 = conv fused (relu, h+=, skip+=),
//      4 = dual-output encoder|skip (cols<256 -> C(+emb), cols>=256 -> skipb)
// AMODE: 0 = plain A, 1 = conv gather (dil), 2 = A + A2
template<int EPI, int AMODE, int ACVT>
__global__ void __launch_bounds__(256, 3) gemm_tc(
    const float* __restrict__ A, const float* __restrict__ A2,
    const float* __restrict__ B, const float* __restrict__ bias,
    float* __restrict__ C, int N, int Kd, int dil, int first,
    float* __restrict__ skipb,
    const float* __restrict__ aux1, const float* __restrict__ aux2)
{
    __shared__ __align__(16) float As[2][128][20];
    __shared__ __align__(16) float Bs[2][16][68];

    int tid = threadIdx.x, lane = tid & 31, w = tid >> 5;
    int bm = blockIdx.y << 7, bn = blockIdx.x << 6;
    int wm = w >> 1, wn = w & 1;
    int r = lane >> 2, cg = lane & 3;
    int ntile = N >> 6;

    float4 acc[2][4];
#pragma unroll
    for (int mt = 0; mt < 2; mt++)
#pragma unroll
        for (int nt = 0; nt < 4; nt++) acc[mt][nt] = make_float4(0.f, 0.f, 0.f, 0.f);

    int arow = tid >> 2, akq = (tid & 3) << 2;
    int KT = Kd >> 4;   // always even here (4, 16, 48)

    // hoisted ldmatrix bases (stage 0/1)
    uint32_t aB0 = (uint32_t)__cvta_generic_to_shared(
        &As[0][(wm << 5) + (lane & 15)][(lane >> 4) << 2]);
    uint32_t aB1 = aB0 + 128u * 20u * 4u;
    // hoisted B fragment indexing: float4 row stride = 17, column = cg*17-ish
    int fidx = (r << 1) + wn;
    int bOff = cg * 17 + fidx;          // float4 index of [cg][fidx]
    const float4* Bf0 = (const float4*)&Bs[0][0][0];
    const float4* Bf1 = (const float4*)&Bs[1][0][0];

    auto loadA = [&](int kt, int st) {
        int k0 = kt << 4;
#pragma unroll
        for (int i = 0; i < 2; i++) {
            int m = arow + (i << 6);
            uint32_t dst = (uint32_t)__cvta_generic_to_shared(&As[st][m][akq]);
            if (AMODE == 1) {
                int kg = k0 + akq;
                int tap = kg >> 8;
                int shift = (2 - tap) * dil;
                int node = bm + m;
                int t = (node >> 7) % TT;
                bool ok = (t >= shift);
                const float* src = ok ? (A + (size_t)(node - (shift << 7)) * CC + (kg & 255)) : A;
                cpa16z(dst, src, ok ? 16 : 0);
            } else if (AMODE == 2) {
                size_t off = (size_t)(bm + m) * Kd + k0 + akq;
                float4 a = *(const float4*)(A + off);
                float4 b = *(const float4*)(A2 + off);
                *(float4*)&As[st][m][akq] =
                    make_float4(a.x + b.x, a.y + b.y, a.z + b.z, a.w + b.w);
            } else {
                cpa16(dst, A + (size_t)(bm + m) * Kd + k0 + akq);
            }
        }
    };
    auto loadB = [&](int kt, int st) {
        int k0 = kt << 4;
        int kr = tid >> 4, nc = (tid & 15) << 2;
        uint32_t dst = (uint32_t)__cvta_generic_to_shared(&Bs[st][kr][nc]);
        cpa16(dst, B + ((size_t)(k0 + kr) * ntile + blockIdx.x) * 64 + nc);
    };

    auto compute = [&](uint32_t aBase, const float4* Bf) {
#pragma unroll
        for (int kk = 0; kk < 16; kk += 8) {
            uint32_t ah[2][4];
            ldmA(ah[0], aBase + (uint32_t)(kk * 4));
            ldmA(ah[1], aBase + (uint32_t)((16 * 20 + kk) * 4));
            if (ACVT) {
#pragma unroll
                for (int mt = 0; mt < 2; mt++)
#pragma unroll
                    for (int q = 0; q < 4; q++)
                        ah[mt][q] = U32F(tf32r(__uint_as_float(ah[mt][q])));
            }
            float4 b0v = Bf[kk * 17 + bOff];
            float4 b1v = Bf[(kk + 4) * 17 + bOff];
            float b0a[4] = {b0v.x, b0v.y, b0v.z, b0v.w};
            float b1a[4] = {b1v.x, b1v.y, b1v.z, b1v.w};
#pragma unroll
            for (int nt = 0; nt < 4; nt++) {
#pragma unroll
                for (int mt = 0; mt < 2; mt++)
                    mma8(acc[mt][nt], ah[mt], U32F(b0a[nt]), U32F(b1a[nt]));
            }
        }
    };

    loadA(0, 0); loadB(0, 0);
    CPA_COMMIT();

    for (int kt = 0; kt < KT; kt += 2) {
        // stage 0
        loadA(kt + 1, 1); loadB(kt + 1, 1);
        CPA_COMMIT();
        CPA_WAIT(1);
        __syncthreads();
        compute(aB0, Bf0);
        __syncthreads();
        // stage 1
        if (kt + 2 < KT) {
            loadA(kt + 2, 0); loadB(kt + 2, 0);
            CPA_COMMIT();
            CPA_WAIT(1);
        } else {
            CPA_WAIT(0);
        }
        __syncthreads();
        compute(aB1, Bf1);
        __syncthreads();
    }

    // ---- epilogue (fragment mapping unchanged) ----
#pragma unroll
    for (int mt = 0; mt < 2; mt++) {
        int m0 = bm + (wm << 5) + (mt << 4) + r;
        int m1 = m0 + 8;
#pragma unroll
        for (int nt = 0; nt < 4; nt++) {
            int col = bn + (wn << 5) + (nt << 3) + (cg << 1);
            float b0 = bias ? bias[col] : 0.f;
            float b1 = bias ? bias[col+1] : 0.f;
            float2 v0 = make_float2(acc[mt][nt].x + b0, acc[mt][nt].y + b1);
            float2 v1 = make_float2(acc[mt][nt].z + b0, acc[mt][nt].w + b1);
            if (EPI == 3) {
                v0.x = fmaxf(v0.x, 0.f); v0.y = fmaxf(v0.y, 0.f);
                v1.x = fmaxf(v1.x, 0.f); v1.y = fmaxf(v1.y, 0.f);
                size_t o0 = (size_t)m0 * CC + col, o1 = (size_t)m1 * CC + col;
                float2 h0 = *(const float2*)(A + o0);
                float2 h1 = *(const float2*)(A + o1);
                *(float2*)(C + o0) = make_float2(h0.x + v0.x, h0.y + v0.y);
                *(float2*)(C + o1) = make_float2(h1.x + v1.x, h1.y + v1.y);
                float2 s0, s1;
                if (first) { s0 = v0; s1 = v1; }
                else {
                    float2 p0 = *(const float2*)(skipb + o0);
                    float2 p1 = *(const float2*)(skipb + o1);
                    s0 = make_float2(p0.x + v0.x, p0.y + v0.y);
                    s1 = make_float2(p1.x + v1.x, p1.y + v1.y);
                }
                *(float2*)(skipb + o0) = s0;
                *(float2*)(skipb + o1) = s1;
            } else if (EPI == 4) {
                if (col < 256) {
                    int s0 = (m0 & 127) * CC + col, t0 = ((m0 >> 7) % TT) * CC + col;
                    int s1 = (m1 & 127) * CC + col, t1 = ((m1 >> 7) % TT) * CC + col;
                    v0.x += aux1[s0] + aux2[t0];   v0.y += aux1[s0+1] + aux2[t0+1];
                    v1.x += aux1[s1] + aux2[t1];   v1.y += aux1[s1+1] + aux2[t1+1];
                    *(float2*)(C + (size_t)m0 * CC + col) = v0;
                    *(float2*)(C + (size_t)m1 * CC + col) = v1;
                } else {
                    int cs = col - 256;
                    *(float2*)(skipb + (size_t)m0 * CC + cs) = v0;
                    *(float2*)(skipb + (size_t)m1 * CC + cs) = v1;
                }
            } else {
                *(float2*)(C + (size_t)m0 * N + col) = v0;
                *(float2*)(C + (size_t)m1 * N + col) = v1;
            }
        }
    }
}

// ---------------- weight prep (all write tile-permuted tf32 layout) ----------
__global__ void transpose_w_all(const float* __restrict__ w, float* __restrict__ wt) {
    int idx = blockIdx.x * 256 + threadIdx.x;        // < 3*768*256
    int l = idx / (KK*CC*CC);
    int rem = idx - l * (KK*CC*CC);
    int k = rem >> 8;                 // 0..767 = tap*256 + cin
    int q = rem & 255;
    int tile = q >> 6, p = q & 63;
    int cout = (tile << 6) + PERM64(p);
    int tap = k >> 8, cin = k & 255;
    wt[idx] = tf32r(w[(((size_t)l*CC + cout)*CC + cin)*KK + tap]);
}

__global__ void pack_qkv_kernel(const float* __restrict__ Wq, const float* __restrict__ Wk,
                                const float* __restrict__ Wv, const float* __restrict__ bq,
                                const float* __restrict__ bk, const float* __restrict__ bv,
                                float* __restrict__ W, float* __restrict__ b) {
    int idx = blockIdx.x * 256 + threadIdx.x;        // < 256*768
    int k = idx / 768, q = idx - k * 768;
    int tile = q >> 6, p = q & 63;
    int n = (tile << 6) + PERM64(p);
    int sel = n >> 8, nn = n & 255;
    const float* src = sel == 0 ? Wq : (sel == 1 ? Wk : Wv);
    W[idx] = tf32r(src[k * CC + nn]);
    if (idx < 768) {
        int sel2 = idx >> 8, nn2 = idx & 255;
        const float* bs = sel2 == 0 ? bq : (sel2 == 1 ? bk : bv);
        b[idx] = bs[nn2];
    }
}

__global__ void pack_wlr_kernel(const float* __restrict__ wl, const float* __restrict__ wr,
                                float* __restrict__ W) {
    int idx = blockIdx.x * 256 + threadIdx.x;        // < 3*256*1024
    int l = idx >> 18;
    int rem = idx & 262143;
    int k = rem >> 10, q = rem & 1023;
    int tile = q >> 6, p = q & 63;
    int n = (tile << 6) + PERM64(p);
    float v = (n < 512) ? wl[(size_t)l*CC*512 + k*512 + n]
                        : wr[(size_t)l*CC*512 + k*512 + (n - 512)];
    W[idx] = tf32r(v);
}

// packed enc|skip [64][512] | wo | gate, permuted tf32 + natural-order bias pack
__global__ void prep_small(const float* __restrict__ enc, const float* __restrict__ skp,
                           const float* __restrict__ wo, const float* __restrict__ gate,
                           const float* __restrict__ benc, const float* __restrict__ bskip,
                           float* __restrict__ o, float* __restrict__ bes) {
    int i = blockIdx.x * 256 + threadIdx.x;   // < 163840
    float v;
    if (i < 32768) {
        int k = i >> 9, q = i & 511;
        int tile = q >> 6, p = q & 63;
        int n = (tile << 6) + PERM64(p);
        v = (n < 256) ? enc[(k << 8) + n] : skp[(k << 8) + (n - 256)];
    } else if (i < 98304) {
        int i2 = i - 32768;
        int k = i2 >> 8, q = i2 & 255;
        int tile = q >> 6, p = q & 63;
        v = wo[(k << 8) + (tile << 6) + PERM64(p)];
    } else {
        int i2 = i - 98304;
        int k = i2 >> 8, q = i2 & 255;
        int tile = q >> 6, p = q & 63;
        v = gate[(k << 8) + (tile << 6) + PERM64(p)];
    }
    o[i] = tf32r(v);
    if (i < 512) bes[i] = (i < 256) ? benc[i] : bskip[i - 256];
}

// ---------------- fused GAT with smem edge cache ----------------
#define GAT_SMEM ((1024 + ECAP*512) * 4)
__global__ void __launch_bounds__(256) gat_fused_kernel(
    const int* __restrict__ edge, const float* __restrict__ xlr,
    const float* __restrict__ att,
    const float* __restrict__ gatb, const float* __restrict__ gamma,
    const float* __restrict__ beta, float* __restrict__ h)
{
    extern __shared__ float gsm[];
    float* xr_sh  = gsm;            // 512
    float* att_sh = gsm + 512;      // 512 (reused as LN reduce buffer)
    float* xe     = gsm + 1024;     // ECAP * 512

    __shared__ float2 logit_sh[MAXE];
    __shared__ float sh_m[2], sh_d[2], sw0[MAXE], sw1[MAXE];
    __shared__ int s_si[MAXE];

    int i = blockIdx.x;
    int tid = threadIdx.x, lane = tid & 31, w = tid >> 5;
    int g = i >> 7, n = i & 127;
    int p0 = d_csr_ptr[n], p1 = d_csr_ptr[n+1];
    int nE = p1 - p0 + 1;     // + self loop (j=0)

    xr_sh[tid]       = xlr[(size_t)i*1024 + 512 + tid];
    xr_sh[256 + tid] = xlr[(size_t)i*1024 + 768 + tid];
    att_sh[tid]       = att[tid];
    att_sh[256 + tid] = att[256 + tid];
    if (tid < nE)
        s_si[tid] = (tid == 0) ? i : ((g << 7) + edge[d_csr_eid[p0 + tid - 1]]);
    __syncthreads();

    for (int j = w; j < nE; j += 8) {
        const float* px = xlr + (size_t)s_si[j] * 1024;
        float* xc = xe + j * 512;
        float s0 = 0.f, s1 = 0.f;
        for (int c = lane; c < 256; c += 32) {
            float x0 = px[c], x1 = px[256 + c];
            if (j < ECAP) { xc[c] = x0; xc[256 + c] = x1; }
            float v0 = x0 + xr_sh[c];
            v0 = v0 > 0.f ? v0 : 0.2f * v0;
            s0 = fmaf(att_sh[c], v0, s0);
            float v1 = x1 + xr_sh[256 + c];
            v1 = v1 > 0.f ? v1 : 0.2f * v1;
            s1 = fmaf(att_sh[256 + c], v1, s1);
        }
#pragma unroll
        for (int o = 16; o; o >>= 1) {
            s0 += __shfl_xor_sync(0xffffffffu, s0, o);
            s1 += __shfl_xor_sync(0xffffffffu, s1, o);
        }
        if (lane == 0) logit_sh[j] = make_float2(s0, s1);
    }
    __syncthreads();

    if (w < 2) {
        float m = -1e30f;
        for (int j = lane; j < nE; j += 32) {
            float lv = (w == 0) ? logit_sh[j].x : logit_sh[j].y;
            m = fmaxf(m, lv);
        }
#pragma unroll
        for (int o = 16; o; o >>= 1) m = fmaxf(m, __shfl_xor_sync(0xffffffffu, m, o));
        float den = 0.f;
        for (int j = lane; j < nE; j += 32) {
            float lv = (w == 0) ? logit_sh[j].x : logit_sh[j].y;
            den += expf(lv - m);
        }
#pragma unroll
        for (int o = 16; o; o >>= 1) den += __shfl_xor_sync(0xffffffffu, den, o);
        if (lane == 0) { sh_m[w] = m; sh_d[w] = den; }
    }
    __syncthreads();
    if (tid < nE) {
        sw0[tid] = expf(logit_sh[tid].x - sh_m[0]);
        sw1[tid] = expf(logit_sh[tid].y - sh_m[1]);
    }
    __syncthreads();

    int c = tid;
    float acc0 = 0.f, acc1 = 0.f;
    for (int j = 0; j < nE; j++) {
        const float* xp = (j < ECAP) ? (xe + j * 512)
                                     : (xlr + (size_t)s_si[j] * 1024);
        acc0 = fmaf(sw0[j], xp[c], acc0);
        acc1 = fmaf(sw1[j], xp[256 + c], acc1);
    }
    float hg = 0.5f * (acc0 / (sh_d[0] + 1e-16f) + acc1 / (sh_d[1] + 1e-16f)) + gatb[c];
    float v = h[(size_t)i*CC + c] + hg;

    float* sred = att_sh;
    sred[c] = v; __syncthreads();
#pragma unroll
    for (int s = 128; s; s >>= 1) { if (c < s) sred[c] += sred[c + s]; __syncthreads(); }
    float mean = sred[0] * (1.f/256.f); __syncthreads();
    float d = v - mean;
    sred[c] = d * d; __syncthreads();
#pragma unroll
    for (int s = 128; s; s >>= 1) { if (c < s) sred[c] += sred[c + s]; __syncthreads(); }
    float var = sred[0] * (1.f/256.f);
    h[(size_t)i*CC + c] = d * rsqrtf(var + 1e-5f) * gamma[c] + beta[c];
}

// ---------------- MHA: block per (head, bt), smem-staged K^T and V ----------
#define MHA_SMEM ((64*132 + 128*68 + 8*64 + 8*128) * 4)
__global__ void __launch_bounds__(256) mha_kernel(const float* __restrict__ qkv,
                                                  float* __restrict__ aoh) {
    extern __shared__ float sm[];
    float* sKT = sm;                  // [64][132]
    float* sV  = sm + 64*132;         // [128][68]
    float* sQ  = sV + 128*68;         // [8][64]
    float* sP  = sQ + 8*64;           // [8][128]

    int head = blockIdx.x, bt = blockIdx.y;
    int base = bt << 7;
    int off = head << 6;
    int tid = threadIdx.x, lane = tid & 31, w = tid >> 5;

    for (int idx = tid; idx < 128*64; idx += 256) {
        int j = idx >> 6, d = idx & 63;
        sKT[d*132 + j] = qkv[(size_t)(base + j)*768 + 256 + off + d];
    }
    for (int idx = tid; idx < 128*16; idx += 256) {
        int j = idx >> 4, d4 = (idx & 15) << 2;
        float4 v = *(const float4*)(qkv + (size_t)(base + j)*768 + 512 + off + d4);
        *(float4*)(sV + j*68 + d4) = v;
    }
    __syncthreads();

    for (int it = 0; it < 16; it++) {
        int q = (it << 3) + w;
        sQ[w*64 + lane]      = qkv[(size_t)(base + q)*768 + off + lane];
        sQ[w*64 + 32 + lane] = qkv[(size_t)(base + q)*768 + off + 32 + lane];
        __syncwarp();
        float s0 = 0.f, s1 = 0.f, s2 = 0.f, s3 = 0.f;
#pragma unroll 8
        for (int d = 0; d < 64; d++) {
            float qd = sQ[w*64 + d];
            const float* kr = sKT + d*132;
            s0 = fmaf(qd, kr[lane], s0);
            s1 = fmaf(qd, kr[32 + lane], s1);
            s2 = fmaf(qd, kr[64 + lane], s2);
            s3 = fmaf(qd, kr[96 + lane], s3);
        }
        s0 *= 0.125f; s1 *= 0.125f; s2 *= 0.125f; s3 *= 0.125f;
        float m = fmaxf(fmaxf(s0, s1), fmaxf(s2, s3));
#pragma unroll
        for (int o = 16; o; o >>= 1) m = fmaxf(m, __shfl_xor_sync(0xffffffffu, m, o));
        float e0 = expf(s0 - m), e1 = expf(s1 - m), e2 = expf(s2 - m), e3 = expf(s3 - m);
        float den = e0 + e1 + e2 + e3;
#pragma unroll
        for (int o = 16; o; o >>= 1) den += __shfl_xor_sync(0xffffffffu, den, o);
        float inv = 1.f / den;
        sP[w*128 + lane]      = e0 * inv;
        sP[w*128 + 32 + lane] = e1 * inv;
        sP[w*128 + 64 + lane] = e2 * inv;
        sP[w*128 + 96 + lane] = e3 * inv;
        __syncwarp();
        float o0 = 0.f, o1 = 0.f;
#pragma unroll 4
        for (int j = 0; j < 128; j++) {
            float pw = sP[w*128 + j];
            o0 = fmaf(pw, sV[j*68 + lane], o0);
            o1 = fmaf(pw, sV[j*68 + 32 + lane], o1);
        }
        aoh[(size_t)(base + q)*CC + off + lane]      = o0;
        aoh[(size_t)(base + q)*CC + off + 32 + lane] = o1;
        __syncwarp();
    }
}

// ---------------- residual(skip+h+ao) + LayerNorm ----------------
__global__ void __launch_bounds__(256) resid_ln_kernel(const float* __restrict__ skip,
                                                       const float* __restrict__ h,
                                                       const float* __restrict__ ao,
                                                       const float* __restrict__ gamma,
                                                       const float* __restrict__ beta,
                                                       float* __restrict__ out) {
    int i = blockIdx.x;
    int c = threadIdx.x;
    size_t o = (size_t)i*CC + c;
    float v = skip[o] + h[o] + ao[o];
    __shared__ float sred[256];
    sred[c] = v; __syncthreads();
#pragma unroll
    for (int s = 128; s; s >>= 1) { if (c < s) sred[c] += sred[c + s]; __syncthreads(); }
    float mean = sred[0] * (1.f/256.f); __syncthreads();
    float d = v - mean;
    sred[c] = d * d; __syncthreads();
#pragma unroll
    for (int s = 128; s; s >>= 1) { if (c < s) sred[c] += sred[c + s]; __syncthreads(); }
    float var = sred[0] * (1.f/256.f);
    out[o] = d * rsqrtf(var + 1e-5f) * gamma[c] + beta[c];
}

// ---------------- gate + skip + output head + softplus ----------------
__global__ void __launch_bounds__(256) final_kernel(const float* __restrict__ gpre,
                                                    const float* __restrict__ href,
                                                    const float* __restrict__ skip2,
                                                    const float* __restrict__ W_out,
                                                    const float* __restrict__ b_out,
                                                    float* __restrict__ out) {
    int i = blockIdx.x;
    int c = threadIdx.x;
    float g = 1.f / (1.f + expf(-gpre[(size_t)i*CC + c]));
    float hf = g * href[(size_t)i*CC + c] + (1.f - g) * skip2[(size_t)i*CC + c];
    __shared__ float r0[256], r1[256];
    r0[c] = hf * W_out[c*2 + 0];
    r1[c] = hf * W_out[c*2 + 1];
    __syncthreads();
#pragma unroll
    for (int s = 128; s; s >>= 1) {
        if (c < s) { r0[c] += r0[c + s]; r1[c] += r1[c + s]; }
        __syncthreads();
    }
    if (c == 0) {
        float o0 = r0[0] + b_out[0];
        float o1 = r1[0] + b_out[1];
        out[(size_t)i*2 + 0] = o0;
        out[(size_t)i*2 + 1] = fmaxf(o1, 0.f) + log1pf(expf(-fabsf(o1)));
    }
}

// ---------------- host orchestration ----------------
extern "C" void kernel_launch(void* const* d_in, const int* in_sizes, int n_in,
                              void* d_out, int out_size) {
    const float* x        = (const float*)d_in[0];
    const int*   edge     = (const int*)  d_in[1];
    const float* W_enc    = (const float*)d_in[2];
    const float* b_enc    = (const float*)d_in[3];
    const float* station  = (const float*)d_in[4];
    const float* horizon  = (const float*)d_in[5];
    const float* conv_w   = (const float*)d_in[6];
    const float* conv_b   = (const float*)d_in[7];
    const float* gat_wl   = (const float*)d_in[8];
    const float* gat_wr   = (const float*)d_in[9];
    const float* gat_att  = (const float*)d_in[10];
    const float* gat_b    = (const float*)d_in[11];
    const float* norm_g   = (const float*)d_in[12];
    const float* norm_b   = (const float*)d_in[13];
    const float* Wq       = (const float*)d_in[14];
    const float* Wk       = (const float*)d_in[15];
    const float* Wv       = (const float*)d_in[16];
    const float* Wo       = (const float*)d_in[17];
    const float* bq       = (const float*)d_in[18];
    const float* bk       = (const float*)d_in[19];
    const float* bv       = (const float*)d_in[20];
    const float* bo       = (const float*)d_in[21];
    const float* an_g     = (const float*)d_in[22];
    const float* an_b     = (const float*)d_in[23];
    const float* W_skip   = (const float*)d_in[24];
    const float* b_skip   = (const float*)d_in[25];
    const float* W_gate   = (const float*)d_in[26];
    const float* b_gate   = (const float*)d_in[27];
    const float* W_out    = (const float*)d_in[28];
    const float* b_out    = (const float*)d_in[29];
    float* out = (float*)d_out;

    float* buf = nullptr;
    cudaGetSymbolAddress((void**)&buf, d_buf);
    float* wbuf1 = nullptr;
    cudaGetSymbolAddress((void**)&wbuf1, d_wbuf1);

    float* g_h    = buf + OFF_H;
    float* g_h2   = buf + OFF_H2;
    float* g_skip = buf + OFF_SKIP;
    float* g_y    = buf + OFF_Y;
    float* g_xlr  = buf + OFF_XLR;
    float* g_qkv  = buf + OFF_QKV;
    float* g_ao   = buf + OFF_AO;
    float* g_href = buf + OFF_HREF;
    float* g_bqkv = buf + OFF_BQKV;
    float* g_bes  = buf + OFF_BES;

    float* w_wt   = wbuf1 + WF_WT;
    float* w_wlr  = wbuf1 + WF_WLR;
    float* w_qkv  = wbuf1 + WF_QKV;
    float* w_es   = wbuf1 + WF_ES;
    float* w_wo   = wbuf1 + WF_WO;
    float* w_gate = wbuf1 + WF_GATE;

    const dim3 thr(256);
    const dim3 gN256(CC/64, NNODE/128);           // (4, 96)
    const dim3 gN512(512/64, NNODE/128);          // (8, 96)
    const dim3 gN768(768/64, NNODE/128);          // (12, 96)
    const dim3 gN1024(1024/64, NNODE/128);        // (16, 96)

    cudaFuncSetAttribute(mha_kernel, cudaFuncAttributeMaxDynamicSharedMemorySize, MHA_SMEM);
    cudaFuncSetAttribute(gat_fused_kernel, cudaFuncAttributeMaxDynamicSharedMemorySize,
                         GAT_SMEM);

    // --- launch order keeps the ncu window (-s 5 -c 1, slot 6) on conv l0 ---
    transpose_w_all<<<(LL*KK*CC*CC)/256, thr>>>(conv_w, w_wt);                  // slot 3
    prep_small<<<163840/256, thr>>>(W_enc, W_skip, Wo, W_gate, b_enc, b_skip,
                                    w_es, g_bes);                               // slot 4
    // fused encoder+skip: cols<256 -> g_h (+station+horizon), cols>=256 -> g_y
    gemm_tc<4,0,0><<<gN512, thr>>>(x, nullptr, w_es, g_bes, g_h, 512, FINF,
                                   0, 0, g_y, station, horizon);                // slot 5

    float* hcur = g_h;
    float* hnext = g_h2;

    // conv l0 — PROFILED KERNEL (slot 6)
    gemm_tc<3,1,1><<<gN256, thr>>>(hcur, nullptr, w_wt, conv_b, hnext, CC,
                                   KK*CC, 1, 1, g_skip, nullptr, nullptr);

    build_csr_kernel<<<1, NST>>>(edge);
    pack_wlr_kernel<<<(LL*CC*1024)/256, thr>>>(gat_wl, gat_wr, w_wlr);

    for (int l = 0; l < LL; l++) {
        if (l > 0) {
            int dil = 1 << l;
            gemm_tc<3,1,1><<<gN256, thr>>>(hcur, nullptr, w_wt + (size_t)l*KK*CC*CC,
                                           conv_b + l*CC, hnext, CC, KK*CC, dil, 0,
                                           g_skip, nullptr, nullptr);
        }
        gemm_tc<0,0,0><<<gN1024, thr>>>(hnext, nullptr, w_wlr + (size_t)l*CC*1024,
                                        nullptr, g_xlr, 1024, CC, 0, 0,
                                        nullptr, nullptr, nullptr);
        gat_fused_kernel<<<NNODE, thr, GAT_SMEM>>>(edge, g_xlr, gat_att + l*GHH*CC,
                                                   gat_b + l*CC, norm_g + l*CC,
                                                   norm_b + l*CC, hnext);
        float* tmp = hcur; hcur = hnext; hnext = tmp;
    }

    pack_qkv_kernel<<<(CC*768)/256, thr>>>(Wq, Wk, Wv, bq, bk, bv, w_qkv, g_bqkv);

    // QKV in one GEMM, A = skip + h (fused)
    gemm_tc<0,2,0><<<gN768, thr>>>(g_skip, hcur, w_qkv, g_bqkv, g_qkv, 768, CC, 0, 0,
                                   nullptr, nullptr, nullptr);
    mha_kernel<<<dim3(NHH, NG), thr, MHA_SMEM>>>(g_qkv, g_xlr);
    gemm_tc<0,0,0><<<gN256, thr>>>(g_xlr, nullptr, w_wo, bo, g_ao, CC, CC, 0, 0,
                                   nullptr, nullptr, nullptr);
    resid_ln_kernel<<<NNODE, thr>>>(g_skip, hcur, g_ao, an_g, an_b, g_href);

    // gate + output head (skip branch g_y already computed by fused encoder GEMM)
    gemm_tc<0,0,0><<<gN256, thr>>>(g_href, nullptr, w_gate, b_gate, g_qkv, CC, CC, 0, 0,
                                   nullptr, nullptr, nullptr);
    final_kernel<<<NNODE, thr>>>(g_qkv, g_href, g_y, W_out, b_out, out);

    (void)in_sizes; (void)n_in; (void)out_size;
}

// round 14
// speedup vs baseline: 1.0908x; 1.0908x over previous
#include <cuda_runtime.h>
#include <math.h>
#include <stdint.h>

// ---------------- problem constants ----------------
#define BBATCH 4
#define TT     24
#define NST    128
#define FINF   64
#define CC     256
#define LL     3
#define KK     3
#define GHH    2
#define NHH    4
#define EE     1024
#define NG     (BBATCH*TT)        // 96
#define NNODE  (NG*NST)           // 12288
#define MAXE   64
#define ECAP   24

// inverse/forward 64-tile permutation (involution): swap 3-bit fields
#define PERM64(p) ((((p) & 7) << 3) | ((p) >> 3))

// ---------------- static scratch ----------------
__device__ int d_csr_ptr[NST+1];
__device__ int d_csr_eid[EE];

#define OFF_H    ((size_t)0)
#define OFF_H2   (OFF_H    + (size_t)NNODE*CC)
#define OFF_SKIP (OFF_H2   + (size_t)NNODE*CC)
#define OFF_Y    (OFF_SKIP + (size_t)NNODE*CC)
#define OFF_XLR  (OFF_Y    + (size_t)NNODE*CC)
#define OFF_QKV  (OFF_XLR  + (size_t)NNODE*1024)
#define OFF_AO   (OFF_QKV  + (size_t)NNODE*768)
#define OFF_HREF (OFF_AO   + (size_t)NNODE*CC)
#define OFF_BQKV (OFF_HREF + (size_t)NNODE*CC)
#define OFF_BES  (OFF_BQKV + (size_t)768)
#define TOTF     (OFF_BES  + (size_t)512)
__device__ float d_buf[TOTF];

// all weights tf32-rounded float, tile-permuted layout
#define WF_WT   ((size_t)0)                        // 3*768*256 conv (transposed)
#define WF_WLR  (WF_WT   + (size_t)LL*KK*CC*CC)    // 3*256*1024
#define WF_QKV  (WF_WLR  + (size_t)LL*CC*1024)     // 256*768
#define WF_ES   (WF_QKV  + (size_t)CC*768)         // 64*512 packed enc|skip
#define WF_WO   (WF_ES   + (size_t)FINF*512)       // 256*256
#define WF_GATE (WF_WO   + (size_t)CC*CC)
#define TOTWF   (WF_GATE + (size_t)CC*CC)
__device__ float d_wbuf1[TOTWF];

// ---------------- helpers ----------------
__device__ __forceinline__ float tf32r(float x) {
    uint32_t u;
    asm("cvt.rna.tf32.f32 %0, %1;" : "=r"(u) : "f"(x));
    return __uint_as_float(u);
}
#define U32F(f) __float_as_uint(f)

__device__ __forceinline__ void mma8(float4& d, const uint32_t a[4],
                                     uint32_t b0, uint32_t b1) {
    asm volatile(
        "mma.sync.aligned.m16n8k8.row.col.f32.tf32.tf32.f32 "
        "{%0,%1,%2,%3},{%4,%5,%6,%7},{%8,%9},{%0,%1,%2,%3};"
        : "+f"(d.x), "+f"(d.y), "+f"(d.z), "+f"(d.w)
        : "r"(a[0]), "r"(a[1]), "r"(a[2]), "r"(a[3]), "r"(b0), "r"(b1));
}

// one ldmatrix.x4 loads the full m16k8 tf32 A fragment (4x 8x4-f32 tiles)
__device__ __forceinline__ void ldmA(uint32_t a[4], uint32_t addr) {
    asm volatile("ldmatrix.sync.aligned.m8n8.x4.shared.b16 {%0,%1,%2,%3}, [%4];"
                 : "=r"(a[0]), "=r"(a[1]), "=r"(a[2]), "=r"(a[3]) : "r"(addr));
}

__device__ __forceinline__ void cpa16(uint32_t dst, const void* src) {
    asm volatile("cp.async.ca.shared.global [%0], [%1], 16;" :: "r"(dst), "l"(src));
}
__device__ __forceinline__ void cpa16z(uint32_t dst, const void* src, int sz) {
    asm volatile("cp.async.ca.shared.global [%0], [%1], 16, %2;"
                 :: "r"(dst), "l"(src), "r"(sz));
}
#define CPA_COMMIT() asm volatile("cp.async.commit_group;" ::: "memory")
#define CPA_WAIT(n)  asm volatile("cp.async.wait_group %0;" :: "n"(n) : "memory")

// ---------------- deterministic CSR of base graph ----------------
__global__ void build_csr_kernel(const int* __restrict__ edge) {
    const int* dst = edge + EE;
    int n = threadIdx.x;
    __shared__ int counts[NST];
    int cnt = 0;
    for (int e = 0; e < EE; e++) if (dst[e] == n) cnt++;
    counts[n] = cnt;
    __syncthreads();
    if (n == 0) {
        int s = 0;
        for (int i = 0; i < NST; i++) { d_csr_ptr[i] = s; s += counts[i]; }
        d_csr_ptr[NST] = s;
    }
    __syncthreads();
    int p = d_csr_ptr[n];
    for (int e = 0; e < EE; e++) if (dst[e] == n) d_csr_eid[p++] = e;  // stable
}

// ---------------- tf32 GEMM: BM=128 BN=64 BK=16, ldmatrix-A + permuted-B -----
// kt loop unrolled by 2: compile-time stage, hoisted addressing.
// ACVT : 1 = RNA-round A fragments (conv spine), 0 = raw fp32 bits
// EPI: 0 = +bias, 3 = conv fused (relu, h+=, skip+=),
//      4 = dual-output encoder|skip (cols<256 -> C(+emb), cols>=256 -> skipb)
// AMODE: 0 = plain A, 1 = conv gather (dil), 2 = A + A2
template<int EPI, int AMODE, int ACVT>
__global__ void __launch_bounds__(256, 3) gemm_tc(
    const float* __restrict__ A, const float* __restrict__ A2,
    const float* __restrict__ B, const float* __restrict__ bias,
    float* __restrict__ C, int N, int Kd, int dil, int first,
    float* __restrict__ skipb,
    const float* __restrict__ aux1, const float* __restrict__ aux2)
{
    __shared__ __align__(16) float As[2][128][20];
    __shared__ __align__(16) float Bs[2][16][68];

    int tid = threadIdx.x, lane = tid & 31, w = tid >> 5;
    int bm = blockIdx.y << 7, bn = blockIdx.x << 6;
    int wm = w >> 1, wn = w & 1;
    int r = lane >> 2, cg = lane & 3;
    int ntile = N >> 6;

    float4 acc[2][4];
#pragma unroll
    for (int mt = 0; mt < 2; mt++)
#pragma unroll
        for (int nt = 0; nt < 4; nt++) acc[mt][nt] = make_float4(0.f, 0.f, 0.f, 0.f);

    int arow = tid >> 2, akq = (tid & 3) << 2;
    int KT = Kd >> 4;   // always even here (4, 16, 48)

    uint32_t aB0 = (uint32_t)__cvta_generic_to_shared(
        &As[0][(wm << 5) + (lane & 15)][(lane >> 4) << 2]);
    uint32_t aB1 = aB0 + 128u * 20u * 4u;
    int fidx = (r << 1) + wn;
    int bOff = cg * 17 + fidx;
    const float4* Bf0 = (const float4*)&Bs[0][0][0];
    const float4* Bf1 = (const float4*)&Bs[1][0][0];

    auto loadA = [&](int kt, int st) {
        int k0 = kt << 4;
#pragma unroll
        for (int i = 0; i < 2; i++) {
            int m = arow + (i << 6);
            uint32_t dst = (uint32_t)__cvta_generic_to_shared(&As[st][m][akq]);
            if (AMODE == 1) {
                int kg = k0 + akq;
                int tap = kg >> 8;
                int shift = (2 - tap) * dil;
                int node = bm + m;
                int t = (node >> 7) % TT;
                bool ok = (t >= shift);
                const float* src = ok ? (A + (size_t)(node - (shift << 7)) * CC + (kg & 255)) : A;
                cpa16z(dst, src, ok ? 16 : 0);
            } else if (AMODE == 2) {
                size_t off = (size_t)(bm + m) * Kd + k0 + akq;
                float4 a = *(const float4*)(A + off);
                float4 b = *(const float4*)(A2 + off);
                *(float4*)&As[st][m][akq] =
                    make_float4(a.x + b.x, a.y + b.y, a.z + b.z, a.w + b.w);
            } else {
                cpa16(dst, A + (size_t)(bm + m) * Kd + k0 + akq);
            }
        }
    };
    auto loadB = [&](int kt, int st) {
        int k0 = kt << 4;
        int kr = tid >> 4, nc = (tid & 15) << 2;
        uint32_t dst = (uint32_t)__cvta_generic_to_shared(&Bs[st][kr][nc]);
        cpa16(dst, B + ((size_t)(k0 + kr) * ntile + blockIdx.x) * 64 + nc);
    };

    auto compute = [&](uint32_t aBase, const float4* Bf) {
#pragma unroll
        for (int kk = 0; kk < 16; kk += 8) {
            uint32_t ah[2][4];
            ldmA(ah[0], aBase + (uint32_t)(kk * 4));
            ldmA(ah[1], aBase + (uint32_t)((16 * 20 + kk) * 4));
            if (ACVT) {
#pragma unroll
                for (int mt = 0; mt < 2; mt++)
#pragma unroll
                    for (int q = 0; q < 4; q++)
                        ah[mt][q] = U32F(tf32r(__uint_as_float(ah[mt][q])));
            }
            float4 b0v = Bf[kk * 17 + bOff];
            float4 b1v = Bf[(kk + 4) * 17 + bOff];
            float b0a[4] = {b0v.x, b0v.y, b0v.z, b0v.w};
            float b1a[4] = {b1v.x, b1v.y, b1v.z, b1v.w};
#pragma unroll
            for (int nt = 0; nt < 4; nt++) {
#pragma unroll
                for (int mt = 0; mt < 2; mt++)
                    mma8(acc[mt][nt], ah[mt], U32F(b0a[nt]), U32F(b1a[nt]));
            }
        }
    };

    loadA(0, 0); loadB(0, 0);
    CPA_COMMIT();

    for (int kt = 0; kt < KT; kt += 2) {
        loadA(kt + 1, 1); loadB(kt + 1, 1);
        CPA_COMMIT();
        CPA_WAIT(1);
        __syncthreads();
        compute(aB0, Bf0);
        __syncthreads();
        if (kt + 2 < KT) {
            loadA(kt + 2, 0); loadB(kt + 2, 0);
            CPA_COMMIT();
            CPA_WAIT(1);
        } else {
            CPA_WAIT(0);
        }
        __syncthreads();
        compute(aB1, Bf1);
        __syncthreads();
    }

    // ---- epilogue ----
#pragma unroll
    for (int mt = 0; mt < 2; mt++) {
        int m0 = bm + (wm << 5) + (mt << 4) + r;
        int m1 = m0 + 8;
#pragma unroll
        for (int nt = 0; nt < 4; nt++) {
            int col = bn + (wn << 5) + (nt << 3) + (cg << 1);
            float b0 = bias ? bias[col] : 0.f;
            float b1 = bias ? bias[col+1] : 0.f;
            float2 v0 = make_float2(acc[mt][nt].x + b0, acc[mt][nt].y + b1);
            float2 v1 = make_float2(acc[mt][nt].z + b0, acc[mt][nt].w + b1);
            if (EPI == 3) {
                v0.x = fmaxf(v0.x, 0.f); v0.y = fmaxf(v0.y, 0.f);
                v1.x = fmaxf(v1.x, 0.f); v1.y = fmaxf(v1.y, 0.f);
                size_t o0 = (size_t)m0 * CC + col, o1 = (size_t)m1 * CC + col;
                float2 h0 = *(const float2*)(A + o0);
                float2 h1 = *(const float2*)(A + o1);
                *(float2*)(C + o0) = make_float2(h0.x + v0.x, h0.y + v0.y);
                *(float2*)(C + o1) = make_float2(h1.x + v1.x, h1.y + v1.y);
                float2 s0, s1;
                if (first) { s0 = v0; s1 = v1; }
                else {
                    float2 p0 = *(const float2*)(skipb + o0);
                    float2 p1 = *(const float2*)(skipb + o1);
                    s0 = make_float2(p0.x + v0.x, p0.y + v0.y);
                    s1 = make_float2(p1.x + v1.x, p1.y + v1.y);
                }
                *(float2*)(skipb + o0) = s0;
                *(float2*)(skipb + o1) = s1;
            } else if (EPI == 4) {
                if (col < 256) {
                    int s0 = (m0 & 127) * CC + col, t0 = ((m0 >> 7) % TT) * CC + col;
                    int s1 = (m1 & 127) * CC + col, t1 = ((m1 >> 7) % TT) * CC + col;
                    v0.x += aux1[s0] + aux2[t0];   v0.y += aux1[s0+1] + aux2[t0+1];
                    v1.x += aux1[s1] + aux2[t1];   v1.y += aux1[s1+1] + aux2[t1+1];
                    *(float2*)(C + (size_t)m0 * CC + col) = v0;
                    *(float2*)(C + (size_t)m1 * CC + col) = v1;
                } else {
                    int cs = col - 256;
                    *(float2*)(skipb + (size_t)m0 * CC + cs) = v0;
                    *(float2*)(skipb + (size_t)m1 * CC + cs) = v1;
                }
            } else {
                *(float2*)(C + (size_t)m0 * N + col) = v0;
                *(float2*)(C + (size_t)m1 * N + col) = v1;
            }
        }
    }
}

// ---------------- weight prep (all write tile-permuted tf32 layout) ----------
__global__ void transpose_w_all(const float* __restrict__ w, float* __restrict__ wt) {
    int idx = blockIdx.x * 256 + threadIdx.x;        // < 3*768*256
    int l = idx / (KK*CC*CC);
    int rem = idx - l * (KK*CC*CC);
    int k = rem >> 8;
    int q = rem & 255;
    int tile = q >> 6, p = q & 63;
    int cout = (tile << 6) + PERM64(p);
    int tap = k >> 8, cin = k & 255;
    wt[idx] = tf32r(w[(((size_t)l*CC + cout)*CC + cin)*KK + tap]);
}

__global__ void pack_qkv_kernel(const float* __restrict__ Wq, const float* __restrict__ Wk,
                                const float* __restrict__ Wv, const float* __restrict__ bq,
                                const float* __restrict__ bk, const float* __restrict__ bv,
                                float* __restrict__ W, float* __restrict__ b) {
    int idx = blockIdx.x * 256 + threadIdx.x;        // < 256*768
    int k = idx / 768, q = idx - k * 768;
    int tile = q >> 6, p = q & 63;
    int n = (tile << 6) + PERM64(p);
    int sel = n >> 8, nn = n & 255;
    const float* src = sel == 0 ? Wq : (sel == 1 ? Wk : Wv);
    W[idx] = tf32r(src[k * CC + nn]);
    if (idx < 768) {
        int sel2 = idx >> 8, nn2 = idx & 255;
        const float* bs = sel2 == 0 ? bq : (sel2 == 1 ? bk : bv);
        b[idx] = bs[nn2];
    }
}

__global__ void pack_wlr_kernel(const float* __restrict__ wl, const float* __restrict__ wr,
                                float* __restrict__ W) {
    int idx = blockIdx.x * 256 + threadIdx.x;        // < 3*256*1024
    int l = idx >> 18;
    int rem = idx & 262143;
    int k = rem >> 10, q = rem & 1023;
    int tile = q >> 6, p = q & 63;
    int n = (tile << 6) + PERM64(p);
    float v = (n < 512) ? wl[(size_t)l*CC*512 + k*512 + n]
                        : wr[(size_t)l*CC*512 + k*512 + (n - 512)];
    W[idx] = tf32r(v);
}

__global__ void prep_small(const float* __restrict__ enc, const float* __restrict__ skp,
                           const float* __restrict__ wo, const float* __restrict__ gate,
                           const float* __restrict__ benc, const float* __restrict__ bskip,
                           float* __restrict__ o, float* __restrict__ bes) {
    int i = blockIdx.x * 256 + threadIdx.x;   // < 163840
    float v;
    if (i < 32768) {
        int k = i >> 9, q = i & 511;
        int tile = q >> 6, p = q & 63;
        int n = (tile << 6) + PERM64(p);
        v = (n < 256) ? enc[(k << 8) + n] : skp[(k << 8) + (n - 256)];
    } else if (i < 98304) {
        int i2 = i - 32768;
        int k = i2 >> 8, q = i2 & 255;
        int tile = q >> 6, p = q & 63;
        v = wo[(k << 8) + (tile << 6) + PERM64(p)];
    } else {
        int i2 = i - 98304;
        int k = i2 >> 8, q = i2 & 255;
        int tile = q >> 6, p = q & 63;
        v = gate[(k << 8) + (tile << 6) + PERM64(p)];
    }
    o[i] = tf32r(v);
    if (i < 512) bes[i] = (i < 256) ? benc[i] : bskip[i - 256];
}

// ---------------- fused GAT: shuffle-based LN (1 barrier) ----------------
#define GAT_SMEM ((1024 + ECAP*512) * 4)
__global__ void __launch_bounds__(256) gat_fused_kernel(
    const int* __restrict__ edge, const float* __restrict__ xlr,
    const float* __restrict__ att,
    const float* __restrict__ gatb, const float* __restrict__ gamma,
    const float* __restrict__ beta, float* __restrict__ h)
{
    extern __shared__ float gsm[];
    float* xr_sh  = gsm;            // 512
    float* att_sh = gsm + 512;      // 512
    float* xe     = gsm + 1024;     // ECAP * 512

    __shared__ float2 logit_sh[MAXE];
    __shared__ float sh_m[2], sh_d[2], sw0[MAXE], sw1[MAXE];
    __shared__ int s_si[MAXE];
    __shared__ float2 part[8];

    int i = blockIdx.x;
    int tid = threadIdx.x, lane = tid & 31, w = tid >> 5;
    int g = i >> 7, n = i & 127;
    int p0 = d_csr_ptr[n], p1 = d_csr_ptr[n+1];
    int nE = p1 - p0 + 1;

    xr_sh[tid]       = xlr[(size_t)i*1024 + 512 + tid];
    xr_sh[256 + tid] = xlr[(size_t)i*1024 + 768 + tid];
    att_sh[tid]       = att[tid];
    att_sh[256 + tid] = att[256 + tid];
    if (tid < nE)
        s_si[tid] = (tid == 0) ? i : ((g << 7) + edge[d_csr_eid[p0 + tid - 1]]);
    __syncthreads();

    for (int j = w; j < nE; j += 8) {
        const float* px = xlr + (size_t)s_si[j] * 1024;
        float* xc = xe + j * 512;
        float s0 = 0.f, s1 = 0.f;
        for (int c = lane; c < 256; c += 32) {
            float x0 = px[c], x1 = px[256 + c];
            if (j < ECAP) { xc[c] = x0; xc[256 + c] = x1; }
            float v0 = x0 + xr_sh[c];
            v0 = v0 > 0.f ? v0 : 0.2f * v0;
            s0 = fmaf(att_sh[c], v0, s0);
            float v1 = x1 + xr_sh[256 + c];
            v1 = v1 > 0.f ? v1 : 0.2f * v1;
            s1 = fmaf(att_sh[256 + c], v1, s1);
        }
#pragma unroll
        for (int o = 16; o; o >>= 1) {
            s0 += __shfl_xor_sync(0xffffffffu, s0, o);
            s1 += __shfl_xor_sync(0xffffffffu, s1, o);
        }
        if (lane == 0) logit_sh[j] = make_float2(s0, s1);
    }
    __syncthreads();

    if (w < 2) {
        float m = -1e30f;
        for (int j = lane; j < nE; j += 32) {
            float lv = (w == 0) ? logit_sh[j].x : logit_sh[j].y;
            m = fmaxf(m, lv);
        }
#pragma unroll
        for (int o = 16; o; o >>= 1) m = fmaxf(m, __shfl_xor_sync(0xffffffffu, m, o));
        float den = 0.f;
        for (int j = lane; j < nE; j += 32) {
            float lv = (w == 0) ? logit_sh[j].x : logit_sh[j].y;
            den += expf(lv - m);
        }
#pragma unroll
        for (int o = 16; o; o >>= 1) den += __shfl_xor_sync(0xffffffffu, den, o);
        if (lane == 0) { sh_m[w] = m; sh_d[w] = den; }
    }
    __syncthreads();
    if (tid < nE) {
        sw0[tid] = expf(logit_sh[tid].x - sh_m[0]);
        sw1[tid] = expf(logit_sh[tid].y - sh_m[1]);
    }
    __syncthreads();

    int c = tid;
    float acc0 = 0.f, acc1 = 0.f;
    for (int j = 0; j < nE; j++) {
        const float* xp = (j < ECAP) ? (xe + j * 512)
                                     : (xlr + (size_t)s_si[j] * 1024);
        acc0 = fmaf(sw0[j], xp[c], acc0);
        acc1 = fmaf(sw1[j], xp[256 + c], acc1);
    }
    float hg = 0.5f * (acc0 / (sh_d[0] + 1e-16f) + acc1 / (sh_d[1] + 1e-16f)) + gatb[c];
    float v = h[(size_t)i*CC + c] + hg;

    // shuffle LN: one barrier
    float sum = v, sq = v * v;
#pragma unroll
    for (int o = 16; o; o >>= 1) {
        sum += __shfl_xor_sync(0xffffffffu, sum, o);
        sq  += __shfl_xor_sync(0xffffffffu, sq, o);
    }
    if (lane == 0) part[w] = make_float2(sum, sq);
    __syncthreads();
    float ts = 0.f, tq = 0.f;
#pragma unroll
    for (int p = 0; p < 8; p++) { ts += part[p].x; tq += part[p].y; }
    float mean = ts * (1.f/256.f);
    float var = tq * (1.f/256.f) - mean * mean;
    h[(size_t)i*CC + c] = (v - mean) * rsqrtf(var + 1e-5f) * gamma[c] + beta[c];
}

// ---------------- MHA: block per (head, bt), smem-staged K^T and V ----------
#define MHA_SMEM ((64*132 + 128*68 + 8*64 + 8*128) * 4)
__global__ void __launch_bounds__(256) mha_kernel(const float* __restrict__ qkv,
                                                  float* __restrict__ aoh) {
    extern __shared__ float sm[];
    float* sKT = sm;
    float* sV  = sm + 64*132;
    float* sQ  = sV + 128*68;
    float* sP  = sQ + 8*64;

    int head = blockIdx.x, bt = blockIdx.y;
    int base = bt << 7;
    int off = head << 6;
    int tid = threadIdx.x, lane = tid & 31, w = tid >> 5;

    for (int idx = tid; idx < 128*64; idx += 256) {
        int j = idx >> 6, d = idx & 63;
        sKT[d*132 + j] = qkv[(size_t)(base + j)*768 + 256 + off + d];
    }
    for (int idx = tid; idx < 128*16; idx += 256) {
        int j = idx >> 4, d4 = (idx & 15) << 2;
        float4 v = *(const float4*)(qkv + (size_t)(base + j)*768 + 512 + off + d4);
        *(float4*)(sV + j*68 + d4) = v;
    }
    __syncthreads();

    for (int it = 0; it < 16; it++) {
        int q = (it << 3) + w;
        sQ[w*64 + lane]      = qkv[(size_t)(base + q)*768 + off + lane];
        sQ[w*64 + 32 + lane] = qkv[(size_t)(base + q)*768 + off + 32 + lane];
        __syncwarp();
        float s0 = 0.f, s1 = 0.f, s2 = 0.f, s3 = 0.f;
#pragma unroll 8
        for (int d = 0; d < 64; d++) {
            float qd = sQ[w*64 + d];
            const float* kr = sKT + d*132;
            s0 = fmaf(qd, kr[lane], s0);
            s1 = fmaf(qd, kr[32 + lane], s1);
            s2 = fmaf(qd, kr[64 + lane], s2);
            s3 = fmaf(qd, kr[96 + lane], s3);
        }
        s0 *= 0.125f; s1 *= 0.125f; s2 *= 0.125f; s3 *= 0.125f;
        float m = fmaxf(fmaxf(s0, s1), fmaxf(s2, s3));
#pragma unroll
        for (int o = 16; o; o >>= 1) m = fmaxf(m, __shfl_xor_sync(0xffffffffu, m, o));
        float e0 = expf(s0 - m), e1 = expf(s1 - m), e2 = expf(s2 - m), e3 = expf(s3 - m);
        float den = e0 + e1 + e2 + e3;
#pragma unroll
        for (int o = 16; o; o >>= 1) den += __shfl_xor_sync(0xffffffffu, den, o);
        float inv = 1.f / den;
        sP[w*128 + lane]      = e0 * inv;
        sP[w*128 + 32 + lane] = e1 * inv;
        sP[w*128 + 64 + lane] = e2 * inv;
        sP[w*128 + 96 + lane] = e3 * inv;
        __syncwarp();
        float o0 = 0.f, o1 = 0.f;
#pragma unroll 4
        for (int j = 0; j < 128; j++) {
            float pw = sP[w*128 + j];
            o0 = fmaf(pw, sV[j*68 + lane], o0);
            o1 = fmaf(pw, sV[j*68 + 32 + lane], o1);
        }
        aoh[(size_t)(base + q)*CC + off + lane]      = o0;
        aoh[(size_t)(base + q)*CC + off + 32 + lane] = o1;
        __syncwarp();
    }
}

// ---------------- residual(skip+h+ao) + LayerNorm (shuffle, 1 barrier) -------
__global__ void __launch_bounds__(256) resid_ln_kernel(const float* __restrict__ skip,
                                                       const float* __restrict__ h,
                                                       const float* __restrict__ ao,
                                                       const float* __restrict__ gamma,
                                                       const float* __restrict__ beta,
                                                       float* __restrict__ out) {
    int i = blockIdx.x;
    int c = threadIdx.x, lane = c & 31, w = c >> 5;
    size_t o = (size_t)i*CC + c;
    float v = skip[o] + h[o] + ao[o];
    __shared__ float2 part[8];
    float sum = v, sq = v * v;
#pragma unroll
    for (int off = 16; off; off >>= 1) {
        sum += __shfl_xor_sync(0xffffffffu, sum, off);
        sq  += __shfl_xor_sync(0xffffffffu, sq, off);
    }
    if (lane == 0) part[w] = make_float2(sum, sq);
    __syncthreads();
    float ts = 0.f, tq = 0.f;
#pragma unroll
    for (int p = 0; p < 8; p++) { ts += part[p].x; tq += part[p].y; }
    float mean = ts * (1.f/256.f);
    float var = tq * (1.f/256.f) - mean * mean;
    out[o] = (v - mean) * rsqrtf(var + 1e-5f) * gamma[c] + beta[c];
}

// ---------------- gate + skip + output head + softplus (shuffle) -------------
__global__ void __launch_bounds__(256) final_kernel(const float* __restrict__ gpre,
                                                    const float* __restrict__ href,
                                                    const float* __restrict__ skip2,
                                                    const float* __restrict__ W_out,
                                                    const float* __restrict__ b_out,
                                                    float* __restrict__ out) {
    int i = blockIdx.x;
    int c = threadIdx.x, lane = c & 31, w = c >> 5;
    float g = 1.f / (1.f + expf(-gpre[(size_t)i*CC + c]));
    float hf = g * href[(size_t)i*CC + c] + (1.f - g) * skip2[(size_t)i*CC + c];
    float v0 = hf * W_out[c*2 + 0];
    float v1 = hf * W_out[c*2 + 1];
    __shared__ float2 part[8];
#pragma unroll
    for (int off = 16; off; off >>= 1) {
        v0 += __shfl_xor_sync(0xffffffffu, v0, off);
        v1 += __shfl_xor_sync(0xffffffffu, v1, off);
    }
    if (lane == 0) part[w] = make_float2(v0, v1);
    __syncthreads();
    if (c == 0) {
        float o0 = 0.f, o1 = 0.f;
#pragma unroll
        for (int p = 0; p < 8; p++) { o0 += part[p].x; o1 += part[p].y; }
        o0 += b_out[0];
        o1 += b_out[1];
        out[(size_t)i*2 + 0] = o0;
        out[(size_t)i*2 + 1] = fmaxf(o1, 0.f) + log1pf(expf(-fabsf(o1)));
    }
}

// ---------------- host orchestration ----------------
extern "C" void kernel_launch(void* const* d_in, const int* in_sizes, int n_in,
                              void* d_out, int out_size) {
    const float* x        = (const float*)d_in[0];
    const int*   edge     = (const int*)  d_in[1];
    const float* W_enc    = (const float*)d_in[2];
    const float* b_enc    = (const float*)d_in[3];
    const float* station  = (const float*)d_in[4];
    const float* horizon  = (const float*)d_in[5];
    const float* conv_w   = (const float*)d_in[6];
    const float* conv_b   = (const float*)d_in[7];
    const float* gat_wl   = (const float*)d_in[8];
    const float* gat_wr   = (const float*)d_in[9];
    const float* gat_att  = (const float*)d_in[10];
    const float* gat_b    = (const float*)d_in[11];
    const float* norm_g   = (const float*)d_in[12];
    const float* norm_b   = (const float*)d_in[13];
    const float* Wq       = (const float*)d_in[14];
    const float* Wk       = (const float*)d_in[15];
    const float* Wv       = (const float*)d_in[16];
    const float* Wo       = (const float*)d_in[17];
    const float* bq       = (const float*)d_in[18];
    const float* bk       = (const float*)d_in[19];
    const float* bv       = (const float*)d_in[20];
    const float* bo       = (const float*)d_in[21];
    const float* an_g     = (const float*)d_in[22];
    const float* an_b     = (const float*)d_in[23];
    const float* W_skip   = (const float*)d_in[24];
    const float* b_skip   = (const float*)d_in[25];
    const float* W_gate   = (const float*)d_in[26];
    const float* b_gate   = (const float*)d_in[27];
    const float* W_out    = (const float*)d_in[28];
    const float* b_out    = (const float*)d_in[29];
    float* out = (float*)d_out;

    float* buf = nullptr;
    cudaGetSymbolAddress((void**)&buf, d_buf);
    float* wbuf1 = nullptr;
    cudaGetSymbolAddress((void**)&wbuf1, d_wbuf1);

    float* g_h    = buf + OFF_H;
    float* g_h2   = buf + OFF_H2;
    float* g_skip = buf + OFF_SKIP;
    float* g_y    = buf + OFF_Y;
    float* g_xlr  = buf + OFF_XLR;
    float* g_qkv  = buf + OFF_QKV;
    float* g_ao   = buf + OFF_AO;
    float* g_href = buf + OFF_HREF;
    float* g_bqkv = buf + OFF_BQKV;
    float* g_bes  = buf + OFF_BES;

    float* w_wt   = wbuf1 + WF_WT;
    float* w_wlr  = wbuf1 + WF_WLR;
    float* w_qkv  = wbuf1 + WF_QKV;
    float* w_es   = wbuf1 + WF_ES;
    float* w_wo   = wbuf1 + WF_WO;
    float* w_gate = wbuf1 + WF_GATE;

    const dim3 thr(256);
    const dim3 gN256(CC/64, NNODE/128);           // (4, 96)
    const dim3 gN512(512/64, NNODE/128);          // (8, 96)
    const dim3 gN768(768/64, NNODE/128);          // (12, 96)
    const dim3 gN1024(1024/64, NNODE/128);        // (16, 96)

    cudaFuncSetAttribute(mha_kernel, cudaFuncAttributeMaxDynamicSharedMemorySize, MHA_SMEM);
    cudaFuncSetAttribute(gat_fused_kernel, cudaFuncAttributeMaxDynamicSharedMemorySize,
                         GAT_SMEM);

    // --- launch order keeps the ncu window (-s 5 -c 1, slot 6) on conv l0 ---
    transpose_w_all<<<(LL*KK*CC*CC)/256, thr>>>(conv_w, w_wt);                  // slot 3
    prep_small<<<163840/256, thr>>>(W_enc, W_skip, Wo, W_gate, b_enc, b_skip,
                                    w_es, g_bes);                               // slot 4
    gemm_tc<4,0,0><<<gN512, thr>>>(x, nullptr, w_es, g_bes, g_h, 512, FINF,
                                   0, 0, g_y, station, horizon);                // slot 5

    float* hcur = g_h;
    float* hnext = g_h2;

    // conv l0 — PROFILED KERNEL (slot 6)
    gemm_tc<3,1,1><<<gN256, thr>>>(hcur, nullptr, w_wt, conv_b, hnext, CC,
                                   KK*CC, 1, 1, g_skip, nullptr, nullptr);

    build_csr_kernel<<<1, NST>>>(edge);
    pack_wlr_kernel<<<(LL*CC*1024)/256, thr>>>(gat_wl, gat_wr, w_wlr);

    for (int l = 0; l < LL; l++) {
        if (l > 0) {
            int dil = 1 << l;
            gemm_tc<3,1,1><<<gN256, thr>>>(hcur, nullptr, w_wt + (size_t)l*KK*CC*CC,
                                           conv_b + l*CC, hnext, CC, KK*CC, dil, 0,
                                           g_skip, nullptr, nullptr);
        }
        gemm_tc<0,0,0><<<gN1024, thr>>>(hnext, nullptr, w_wlr + (size_t)l*CC*1024,
                                        nullptr, g_xlr, 1024, CC, 0, 0,
                                        nullptr, nullptr, nullptr);
        gat_fused_kernel<<<NNODE, thr, GAT_SMEM>>>(edge, g_xlr, gat_att + l*GHH*CC,
                                                   gat_b + l*CC, norm_g + l*CC,
                                                   norm_b + l*CC, hnext);
        float* tmp = hcur; hcur = hnext; hnext = tmp;
    }

    pack_qkv_kernel<<<(CC*768)/256, thr>>>(Wq, Wk, Wv, bq, bk, bv, w_qkv, g_bqkv);

    gemm_tc<0,2,0><<<gN768, thr>>>(g_skip, hcur, w_qkv, g_bqkv, g_qkv, 768, CC, 0, 0,
                                   nullptr, nullptr, nullptr);
    mha_kernel<<<dim3(NHH, NG), thr, MHA_SMEM>>>(g_qkv, g_xlr);
    gemm_tc<0,0,0><<<gN256, thr>>>(g_xlr, nullptr, w_wo, bo, g_ao, CC, CC, 0, 0,
                                   nullptr, nullptr, nullptr);
    resid_ln_kernel<<<NNODE, thr>>>(g_skip, hcur, g_ao, an_g, an_b, g_href);

    gemm_tc<0,0,0><<<gN256, thr>>>(g_href, nullptr, w_gate, b_gate, g_qkv, CC, CC, 0, 0,
                                   nullptr, nullptr, nullptr);
    final_kernel<<<NNODE, thr>>>(g_qkv, g_href, g_y, W_out, b_out, out);

    (void)in_sizes; (void)n_in; (void)out_size;
}